// round 1
// baseline (speedup 1.0000x reference)
#include <cuda_runtime.h>
#include <cooperative_groups.h>
#include <math.h>

namespace cg = cooperative_groups;

// ---------------- problem constants ----------------
#define Nn    20000
#define Ee    640000
#define Pp    27
#define Mm    5000
#define MAXNb 64
#define KIN   64
#define PIN   (Pp * KIN)      // 1728
#define R2c   0.01f

// output section offsets (flattened float32 tuple concat)
#define SEC_X     0
#define SEC_COL   320000
#define SEC_ROW   640000
#define SEC_POS   960000
#define SEC_BATCH 975000
#define SEC_EA    980000

// ---------------- persistent device scratch ----------------
__device__ __align__(16) float4 g_pos4[Nn];        // x,y,z, an=|p|^2
__device__ int    g_idx[Mm];
__device__ int    g_selmap[Nn];
__device__ float  g_deg[Mm];
__device__ __align__(16) float g_acc[(size_t)Mm * PIN];   // 34.6 MB

// ---------------- prep: pack pos + squared norm ----------------
__global__ void prep_kernel(const float* __restrict__ pos) {
    int i = blockIdx.x * blockDim.x + threadIdx.x;
    if (i >= Nn) return;
    float x = pos[3 * i], y = pos[3 * i + 1], z = pos[3 * i + 2];
    float an = __fadd_rn(__fadd_rn(__fmul_rn(x, x), __fmul_rn(y, y)), __fmul_rn(z, z));
    g_pos4[i] = make_float4(x, y, z, an);
}

// ---------------- FPS: 8-CTA cluster, SMEM-resident points ----------------
#define FPS_CTAS 8
#define FPS_T    256
#define PTS      (Nn / FPS_CTAS)   // 2500

struct FpsSlot {
    unsigned long long key;
    float x, y, z;
};

__global__ void __cluster_dims__(FPS_CTAS, 1, 1) fps_kernel() {
    __shared__ float4 s_p[PTS];                       // 40 KB
    __shared__ FpsSlot s_slot[2][FPS_CTAS];
    __shared__ unsigned long long s_wkey[FPS_T / 32];

    cg::cluster_group cluster = cg::this_cluster();
    const int rank = cluster.block_rank();
    const int tid  = threadIdx.x;
    const int base = rank * PTS;
    const float INF = __int_as_float(0x7f800000);

    for (int i = tid; i < PTS; i += FPS_T) {
        float4 p = g_pos4[base + i];
        p.w = INF;                                    // mind init
        s_p[i] = p;
    }
    float4 q0 = g_pos4[0];
    float qx = q0.x, qy = q0.y, qz = q0.z;
    if (rank == 0 && tid == 0) g_idx[0] = 0;
    __syncthreads();
    cluster.sync();

    int buf = 0;
    for (int t = 0; t < Mm - 1; ++t) {
        // fused mind update (exact, no FMA) + local argmax
        float bval = -INF;
        int   bidx = 0;
        for (int i = tid; i < PTS; i += FPS_T) {
            float4 p = s_p[i];
            float dx = p.x - qx, dy = p.y - qy, dz = p.z - qz;
            float d2 = __fadd_rn(__fadd_rn(__fmul_rn(dx, dx), __fmul_rn(dy, dy)),
                                 __fmul_rn(dz, dz));
            float nm = fminf(p.w, d2);
            s_p[i].w = nm;
            if (nm > bval) { bval = nm; bidx = base + i; }   // strict > keeps first
        }
        // pack: larger val wins; ties -> smaller global index
        unsigned long long key =
            ((unsigned long long)__float_as_uint(bval) << 32) |
            (unsigned long long)(0xFFFFFFFFu - (unsigned)bidx);
        // warp max-reduce
        #pragma unroll
        for (int o = 16; o; o >>= 1) {
            unsigned long long ok = __shfl_down_sync(0xffffffffu, key, o);
            if (ok > key) key = ok;
        }
        if ((tid & 31) == 0) s_wkey[tid >> 5] = key;
        __syncthreads();
        if (tid < 32) {
            unsigned long long k2 = (tid < (FPS_T / 32)) ? s_wkey[tid] : 0ull;
            #pragma unroll
            for (int o = 4; o; o >>= 1) {
                unsigned long long ok = __shfl_down_sync(0xffffffffu, k2, o);
                if (ok > k2) k2 = ok;
            }
            if (tid == 0) {
                unsigned li = 0xFFFFFFFFu - (unsigned)(k2 & 0xFFFFFFFFull);
                float4 wp = s_p[li - base];
                FpsSlot sl; sl.key = k2; sl.x = wp.x; sl.y = wp.y; sl.z = wp.z;
                #pragma unroll
                for (int r = 0; r < FPS_CTAS; ++r) {
                    FpsSlot* dst = cluster.map_shared_rank(&s_slot[buf][rank], r);
                    *dst = sl;     // push partial (incl. coords) into every CTA
                }
            }
        }
        cluster.sync();
        // everyone picks the global winner locally
        FpsSlot w = s_slot[buf][0];
        #pragma unroll
        for (int r = 1; r < FPS_CTAS; ++r) {
            FpsSlot c = s_slot[buf][r];
            if (c.key > w.key) w = c;
        }
        if (rank == 0 && tid == 0)
            g_idx[t + 1] = (int)(0xFFFFFFFFu - (unsigned)(w.key & 0xFFFFFFFFull));
        qx = w.x; qy = w.y; qz = w.z;
        buf ^= 1;
    }
}

// ---------------- selection map + scratch zeroing ----------------
__global__ void sel_init_kernel() {
    int i = blockIdx.x * blockDim.x + threadIdx.x;
    if (i < Nn) g_selmap[i] = -1;
}
__global__ void sel_set_kernel() {
    int m = blockIdx.x * blockDim.x + threadIdx.x;
    if (m < Mm) { g_selmap[g_idx[m]] = m; g_deg[m] = 0.0f; }
}
__global__ void zero_acc_kernel() {
    size_t i = (size_t)(blockIdx.x) * blockDim.x + threadIdx.x;
    float4* a4 = reinterpret_cast<float4*>(g_acc);
    size_t n4 = ((size_t)Mm * PIN) / 4;
    if (i < n4) a4[i] = make_float4(0.f, 0.f, 0.f, 0.f);
}

// ---------------- spline scatter: warp per edge, filtered by dst ----------------
__global__ void scatter_kernel(const float* __restrict__ x,
                               const int*   __restrict__ ei,
                               const float* __restrict__ ea) {
    int e    = (blockIdx.x * blockDim.x + threadIdx.x) >> 5;
    int lane = threadIdx.x & 31;
    if (e >= Ee) return;
    int dst = ei[Ee + e];
    int c   = g_selmap[dst];
    if (c < 0) return;
    int src = ei[e];

    float v0 = __fmul_rn(ea[3 * e + 0], 2.0f);
    float v1 = __fmul_rn(ea[3 * e + 1], 2.0f);
    float v2 = __fmul_rn(ea[3 * e + 2], 2.0f);
    float k0 = fminf(fmaxf(floorf(v0), 0.f), 1.f);
    float k1 = fminf(fmaxf(floorf(v1), 0.f), 1.f);
    float k2 = fminf(fmaxf(floorf(v2), 0.f), 1.f);
    float f0 = v0 - k0, f1 = v1 - k1, f2 = v2 - k2;
    int kb0 = (int)k0, kb1 = (int)k1, kb2 = (int)k2;

    float xj0 = x[src * KIN + lane];
    float xj1 = x[src * KIN + 32 + lane];
    float* accb = g_acc + (size_t)c * PIN;

    #pragma unroll
    for (int s = 0; s < 8; ++s) {
        int b0 = s & 1, b1 = (s >> 1) & 1, b2 = (s >> 2) & 1;
        float b = b0 ? f0 : (1.0f - f0);
        b = __fmul_rn(b, b1 ? f1 : (1.0f - f1));
        b = __fmul_rn(b, b2 ? f2 : (1.0f - f2));
        int pidx = (kb0 + b0) * 9 + (kb1 + b1) * 3 + (kb2 + b2);
        atomicAdd(&accb[pidx * KIN + lane],      __fmul_rn(b, xj0));
        atomicAdd(&accb[pidx * KIN + 32 + lane], __fmul_rn(b, xj1));
    }
    if (lane == 0) atomicAdd(&g_deg[c], 1.0f);
}

// ---------------- per-node GEMM + root + bias + ELU -> output section 0 ----------------
__global__ void node_out_kernel(const float* __restrict__ x,
                                const float* __restrict__ W,
                                const float* __restrict__ rootw,
                                const float* __restrict__ bias,
                                float* __restrict__ out) {
    int m = blockIdx.x;            // 0..M-1
    int o = threadIdx.x;           // 0..63
    const float* a = g_acc + (size_t)m * PIN;
    float s = 0.f;
    #pragma unroll 8
    for (int k = 0; k < PIN; ++k)
        s += __ldg(&a[k]) * __ldg(&W[k * KIN + o]);
    s /= fmaxf(g_deg[m], 1.0f);
    int node = g_idx[m];
    const float* xr = x + (size_t)node * KIN;
    #pragma unroll 8
    for (int i = 0; i < KIN; ++i)
        s += __ldg(&xr[i]) * __ldg(&rootw[i * KIN + o]);
    s += bias[o];
    s = (s > 0.f) ? s : expm1f(s);
    out[SEC_X + m * KIN + o] = s;
}

// ---------------- radius neighbors: block per query, ordered first-64 ----------------
__global__ void radius_kernel(float* __restrict__ out) {
    __shared__ int s_list[MAXNb];
    __shared__ int s_cnt;
    __shared__ int s_wcnt[4];
    int m = blockIdx.x, tid = threadIdx.x;
    int wid = tid >> 5, lane = tid & 31;
    int node = g_idx[m];
    float4 q = g_pos4[node];        // q.w = qn
    if (tid == 0) s_cnt = 0;
    __syncthreads();

    for (int base = 0; base < Nn; base += 128) {
        int i = base + tid;
        bool val = false;
        if (i < Nn) {
            float4 p = g_pos4[i];
            float dot = __fadd_rn(__fadd_rn(__fmul_rn(q.x, p.x), __fmul_rn(q.y, p.y)),
                                  __fmul_rn(q.z, p.z));
            float d2 = __fadd_rn(__fadd_rn(q.w, p.w), -__fmul_rn(2.0f, dot));
            val = (d2 < R2c);
        }
        unsigned bal = __ballot_sync(0xffffffffu, val);
        if (lane == 0) s_wcnt[wid] = __popc(bal);
        __syncthreads();
        int off = s_cnt;
        for (int w2 = 0; w2 < wid; ++w2) off += s_wcnt[w2];
        off += __popc(bal & ((1u << lane) - 1u));
        if (val && off < MAXNb) s_list[off] = i;
        __syncthreads();
        if (tid == 0) s_cnt += s_wcnt[0] + s_wcnt[1] + s_wcnt[2] + s_wcnt[3];
        __syncthreads();
        if (s_cnt >= MAXNb) break;
    }
    int cnt = min(s_cnt, MAXNb);
    for (int j = tid; j < MAXNb; j += 128) {
        int col = (j < cnt) ? s_list[j] : -1;
        out[SEC_COL + m * MAXNb + j] = (float)col;
        out[SEC_ROW + m * MAXNb + j] = (j < cnt) ? (float)m : -1.0f;
    }
}

// ---------------- tail gathers: pos[idx], batch[idx], edge_attr[idx] ----------------
__global__ void tail_kernel(const float* __restrict__ pos,
                            const float* __restrict__ ea,
                            float* __restrict__ out) {
    int m = blockIdx.x * blockDim.x + threadIdx.x;
    if (m >= Mm) return;
    int node = g_idx[m];
    out[SEC_POS + 3 * m + 0] = pos[3 * node + 0];
    out[SEC_POS + 3 * m + 1] = pos[3 * node + 1];
    out[SEC_POS + 3 * m + 2] = pos[3 * node + 2];
    out[SEC_BATCH + m]       = 0.0f;
    out[SEC_EA + 3 * m + 0]  = ea[3 * node + 0];
    out[SEC_EA + 3 * m + 1]  = ea[3 * node + 1];
    out[SEC_EA + 3 * m + 2]  = ea[3 * node + 2];
}

// ---------------- launch ----------------
extern "C" void kernel_launch(void* const* d_in, const int* in_sizes, int n_in,
                              void* d_out, int out_size) {
    const float* x     = (const float*)d_in[0];
    const int*   ei    = (const int*)d_in[1];
    const float* ea    = (const float*)d_in[2];
    const float* pos   = (const float*)d_in[3];
    // d_in[4] = batch (all zeros, unused)
    const float* W     = (const float*)d_in[5];
    const float* rootw = (const float*)d_in[6];
    const float* bias  = (const float*)d_in[7];
    float* out = (float*)d_out;

    prep_kernel<<<(Nn + 255) / 256, 256>>>(pos);
    fps_kernel<<<FPS_CTAS, FPS_T>>>();
    sel_init_kernel<<<(Nn + 255) / 256, 256>>>();
    sel_set_kernel<<<(Mm + 255) / 256, 256>>>();
    {
        size_t n4 = ((size_t)Mm * PIN) / 4;
        zero_acc_kernel<<<(unsigned)((n4 + 255) / 256), 256>>>();
    }
    scatter_kernel<<<(Ee * 32 + 255) / 256, 256>>>(x, ei, ea);
    node_out_kernel<<<Mm, KIN>>>(x, W, rootw, bias, out);
    radius_kernel<<<Mm, 128>>>(out);
    tail_kernel<<<(Mm + 127) / 128, 128>>>(pos, ea, out);
}